// round 4
// baseline (speedup 1.0000x reference)
#include <cuda_runtime.h>
#include <math.h>

#define DIM 4096
#define HID 8192
#define ALPHA 0.1f
#define LOG_ALPHA -2.3025850929940457f

#define ICHUNK 1024            // columns per stage-1 block (256 thr x 4)
#define BROWS  128             // rows per stage-1 block
#define NSLAB  (HID / BROWS)   // 64 partial slabs
#define ZGRID  592             // persistent single-wave grid for k_z (148 SMs x 4)

// Scratch (device globals). 4 partial arrays, 1 MB each = 4 MB.
static __device__ __align__(16) float g_pAv[(size_t)NSLAB * DIM];
static __device__ __align__(16) float g_pBv[(size_t)NSLAB * DIM];
static __device__ __align__(16) float g_pAw[(size_t)NSLAB * DIM];
static __device__ __align__(16) float g_pBw[(size_t)NSLAB * DIM];
static __device__ __align__(16) float g_Av[DIM];
static __device__ __align__(16) float g_Bv[DIM];
static __device__ __align__(16) float g_Aw[DIM];
static __device__ __align__(16) float g_Bw[DIM];
static __device__ __align__(16) float g_W[DIM + 4];   // W[i], i in [0,DIM]

// ---------------------------------------------------------------------------
__device__ __forceinline__ float block_reduce_256(float val, float* sm) {
#pragma unroll
    for (int o = 16; o > 0; o >>= 1)
        val += __shfl_xor_sync(0xffffffffu, val, o);
    int warp = threadIdx.x >> 5;
    if ((threadIdx.x & 31) == 0) sm[warp] = val;
    __syncthreads();
    if (warp == 0) {
        val = (threadIdx.x < 8) ? sm[threadIdx.x] : 0.f;
#pragma unroll
        for (int o = 4; o > 0; o >>= 1)
            val += __shfl_xor_sync(0xffffffffu, val, o);
    }
    return val;
}

// ---------------------------------------------------------------------------
// Stage-1: ONE pass over x computing all four column statistics per slab.
// grid = (DIM/ICHUNK=4, NSLAB=64) = 256 blocks -> single wave, all resident.
__global__ __launch_bounds__(256) void k_red4(
    const float* __restrict__ x, const float* __restrict__ v,
    const float* __restrict__ w,
    const float* __restrict__ u_p, const float* __restrict__ a_p)
{
    const float u = u_p[0];
    const float a = a_p[0];
    const int i0 = blockIdx.x * ICHUNK + threadIdx.x * 4;
    const int b0 = blockIdx.y * BROWS;
    float4 Av = make_float4(0.f, 0.f, 0.f, 0.f);
    float4 Bv = make_float4(0.f, 0.f, 0.f, 0.f);
    float4 Aw = make_float4(0.f, 0.f, 0.f, 0.f);
    float4 Bw = make_float4(0.f, 0.f, 0.f, 0.f);
    const float* xp = x + (size_t)b0 * DIM + i0;
#pragma unroll 4
    for (int r = 0; r < BROWS; ++r) {
        const float vb = __ldg(&v[b0 + r]);
        const float wb = __ldg(&w[b0 + r]);
        const float4 xv = __ldcs((const float4*)(xp + (size_t)r * DIM));
        const float l0 = fmaf(u, xv.x, a);
        const float l1 = fmaf(u, xv.y, a);
        const float l2 = fmaf(u, xv.z, a);
        const float l3 = fmaf(u, xv.w, a);
        const float r0 = fmaxf(l0, 0.f), r1 = fmaxf(l1, 0.f);
        const float r2 = fmaxf(l2, 0.f), r3 = fmaxf(l3, 0.f);
        Av.x = fmaf(vb, r0, Av.x);  Aw.x = fmaf(wb, r0, Aw.x);
        Av.y = fmaf(vb, r1, Av.y);  Aw.y = fmaf(wb, r1, Aw.y);
        Av.z = fmaf(vb, r2, Av.z);  Aw.z = fmaf(wb, r2, Aw.z);
        Av.w = fmaf(vb, r3, Av.w);  Aw.w = fmaf(wb, r3, Aw.w);
        if (l0 > 0.f) { Bv.x += vb; Bw.x += wb; }
        if (l1 > 0.f) { Bv.y += vb; Bw.y += wb; }
        if (l2 > 0.f) { Bv.z += vb; Bw.z += wb; }
        if (l3 > 0.f) { Bv.w += vb; Bw.w += wb; }
    }
    const size_t po = (size_t)blockIdx.y * DIM + i0;
    __stcs((float4*)&g_pAv[po], Av);
    __stcs((float4*)&g_pBv[po], Bv);
    __stcs((float4*)&g_pAw[po], Aw);
    __stcs((float4*)&g_pBw[po], Bw);
}

// ---------------------------------------------------------------------------
// Stage-2: reduce NSLAB slabs -> A/B vectors. 64 blocks x 256 threads.
// 4 thread-groups of 64 each sum NSLAB/4 slabs, combined in fixed order.
__global__ __launch_bounds__(256) void k_finred4()
{
    __shared__ float sAv[4][64], sBv[4][64], sAw[4][64], sBw[4][64];
    const int col = blockIdx.x * 64 + (threadIdx.x & 63);
    const int grp = threadIdx.x >> 6;                 // 0..3
    const int s0 = grp * (NSLAB / 4);
    float av = 0.f, bv = 0.f, aw = 0.f, bw = 0.f;
#pragma unroll 4
    for (int s = 0; s < NSLAB / 4; ++s) {
        const size_t o = (size_t)(s0 + s) * DIM + col;
        av += g_pAv[o]; bv += g_pBv[o]; aw += g_pAw[o]; bw += g_pBw[o];
    }
    sAv[grp][threadIdx.x & 63] = av;
    sBv[grp][threadIdx.x & 63] = bv;
    sAw[grp][threadIdx.x & 63] = aw;
    sBw[grp][threadIdx.x & 63] = bw;
    __syncthreads();
    if (grp == 0) {
        const int t = threadIdx.x;                    // 0..63
        g_Av[col] = ((sAv[0][t] + sAv[1][t]) + (sAv[2][t] + sAv[3][t]));
        g_Bv[col] = ((sBv[0][t] + sBv[1][t]) + (sBv[2][t] + sBv[3][t]));
        g_Aw[col] = ((sAw[0][t] + sAw[1][t]) + (sAw[2][t] + sAw[3][t]));
        g_Bw[col] = ((sBw[0][t] + sBw[1][t]) + (sBw[2][t] + sBw[3][t]));
    }
}

// ---------------------------------------------------------------------------
// Scan V[i+1] = Av[i] + Bv[i]*V[i] (V[0]=0) via affine-map composition, then
// W[i+1] = Aw[i] + Bw[i]*V[i], W[0]=0. One block, 1024 threads, 4 elems each.
__global__ __launch_bounds__(1024) void k_scanw()
{
    __shared__ float sa[1024];
    __shared__ float sb[1024];
    const int t = threadIdx.x;
    float la[4], lb[4];
    la[0] = g_Av[4 * t];
    lb[0] = g_Bv[4 * t];
#pragma unroll
    for (int k = 1; k < 4; ++k) {
        const float A = g_Av[4 * t + k];
        const float B = g_Bv[4 * t + k];
        la[k] = fmaf(B, la[k - 1], A);
        lb[k] = B * lb[k - 1];
    }
    sa[t] = la[3];
    sb[t] = lb[3];
    __syncthreads();
#pragma unroll
    for (int off = 1; off < 1024; off <<= 1) {
        float pa = 0.f, pb = 0.f;
        const bool has = (t >= off);
        if (has) { pa = sa[t - off]; pb = sb[t - off]; }
        __syncthreads();
        if (has) {
            sa[t] = fmaf(sb[t], pa, sa[t]);
            sb[t] = sb[t] * pb;
        }
        __syncthreads();
    }
    const float pa = (t > 0) ? sa[t - 1] : 0.f;       // V[4t]
    float V[4];
    V[0] = pa;
#pragma unroll
    for (int k = 1; k < 4; ++k)
        V[k] = fmaf(lb[k - 1], pa, la[k - 1]);
#pragma unroll
    for (int k = 0; k < 4; ++k) {
        const int i = 4 * t + k;
        g_W[i + 1] = fmaf(g_Bw[i], V[k], g_Aw[i]);
    }
    if (t == 0) g_W[0] = 0.f;
}

// ---------------------------------------------------------------------------
// Persistent single-wave z kernel: grid-stride over rows.
// z[b,i] = leaky(y*x[b,i] + W_i + b0); logdet[b] = DIM*log|y| + cnt*log(alpha)
__global__ __launch_bounds__(256) void k_z(
    const float* __restrict__ x,
    const float* __restrict__ y_p,
    const float* __restrict__ b_p,
    float* __restrict__ out)
{
    __shared__ float sm[8];
    const float y0 = y_p[0];
    const float bb = b_p[0];
    const float ld_base = (float)DIM * logf(fabsf(y0));

    for (int row = blockIdx.x; row < HID; row += ZGRID) {
        const float4* __restrict__ xr = (const float4*)(x + (size_t)row * DIM);
        float4* __restrict__ zr = (float4*)(out + (size_t)row * DIM);
        float cnt = 0.f;
#pragma unroll
        for (int j = 0; j < DIM / 4 / 256; ++j) {   // 4 iterations
            const int c = j * 256 + threadIdx.x;
            const float4 xv = __ldcs(&xr[c]);
            const float4 wv = __ldg((const float4*)&g_W[4 * c]);
            float4 z;
            const float l0 = fmaf(y0, xv.x, wv.x + bb);
            const float l1 = fmaf(y0, xv.y, wv.y + bb);
            const float l2 = fmaf(y0, xv.z, wv.z + bb);
            const float l3 = fmaf(y0, xv.w, wv.w + bb);
            z.x = (l0 >= 0.f) ? l0 : ALPHA * l0; if (l0 < 0.f) cnt += 1.f;
            z.y = (l1 >= 0.f) ? l1 : ALPHA * l1; if (l1 < 0.f) cnt += 1.f;
            z.z = (l2 >= 0.f) ? l2 : ALPHA * l2; if (l2 < 0.f) cnt += 1.f;
            z.w = (l3 >= 0.f) ? l3 : ALPHA * l3; if (l3 < 0.f) cnt += 1.f;
            __stcs(&zr[c], z);
        }
        const float c = block_reduce_256(cnt, sm);
        if (threadIdx.x == 0)
            out[(size_t)HID * DIM + row] = c * LOG_ALPHA + ld_base;
        __syncthreads();   // sm reuse across row iterations
    }
}

// ---------------------------------------------------------------------------
extern "C" void kernel_launch(void* const* d_in, const int* in_sizes, int n_in,
                              void* d_out, int out_size)
{
    (void)in_sizes; (void)n_in; (void)out_size;
    const float* x = (const float*)d_in[0];   // [HID, DIM]
    const float* y = (const float*)d_in[1];   // [1]
    const float* w = (const float*)d_in[2];   // [HID]
    const float* b = (const float*)d_in[3];   // [1]
    const float* u = (const float*)d_in[4];   // [1]
    const float* v = (const float*)d_in[5];   // [HID]
    const float* a = (const float*)d_in[6];   // [1]
    float* out = (float*)d_out;               // [HID*DIM] z + [HID] logdet

    k_red4<<<dim3(DIM / ICHUNK, NSLAB), 256>>>(x, v, w, u, a);
    k_finred4<<<DIM / 64, 256>>>();
    k_scanw<<<1, 1024>>>();
    k_z<<<ZGRID, 256>>>(x, y, b, out);
}

// round 5
// speedup vs baseline: 1.3783x; 1.3783x over previous
#include <cuda_runtime.h>
#include <math.h>

#define DIM 4096
#define HID 8192
#define ALPHA 0.1f
#define LOG_ALPHA -2.3025850929940457f

#define ICHUNK 1024            // columns per stage-1 block (256 thr x 4)
#define BROWS  64              // rows per stage-1 block
#define NSLAB  (HID / BROWS)   // 128 partial slabs

// Scratch (device globals). 4 partial arrays, 2 MB each = 8 MB.
static __device__ __align__(16) float g_pAv[(size_t)NSLAB * DIM];
static __device__ __align__(16) float g_pBv[(size_t)NSLAB * DIM];
static __device__ __align__(16) float g_pAw[(size_t)NSLAB * DIM];
static __device__ __align__(16) float g_pBw[(size_t)NSLAB * DIM];
static __device__ __align__(16) float g_Av[DIM];
static __device__ __align__(16) float g_Bv[DIM];
static __device__ __align__(16) float g_Aw[DIM];
static __device__ __align__(16) float g_Bw[DIM];
static __device__ __align__(16) float g_W[DIM + 4];   // W[i], i in [0,DIM]

// ---------------------------------------------------------------------------
__device__ __forceinline__ float block_reduce_256(float val, float* sm) {
#pragma unroll
    for (int o = 16; o > 0; o >>= 1)
        val += __shfl_xor_sync(0xffffffffu, val, o);
    int warp = threadIdx.x >> 5;
    if ((threadIdx.x & 31) == 0) sm[warp] = val;
    __syncthreads();
    if (warp == 0) {
        val = (threadIdx.x < 8) ? sm[threadIdx.x] : 0.f;
#pragma unroll
        for (int o = 4; o > 0; o >>= 1)
            val += __shfl_xor_sync(0xffffffffu, val, o);
    }
    return val;
}

// ---------------------------------------------------------------------------
// Stage-1: ONE pass over x computing all four column statistics per slab.
// x loaded with DEFAULT policy (we WANT it resident in L2 for k_z).
// Partials stored with __stcs (evict-first; don't displace x).
__global__ __launch_bounds__(256) void k_red4(
    const float* __restrict__ x, const float* __restrict__ v,
    const float* __restrict__ w,
    const float* __restrict__ u_p, const float* __restrict__ a_p)
{
    const float u = u_p[0];
    const float a = a_p[0];
    const int i0 = blockIdx.x * ICHUNK + threadIdx.x * 4;
    const int b0 = blockIdx.y * BROWS;
    float4 Av = make_float4(0.f, 0.f, 0.f, 0.f);
    float4 Bv = make_float4(0.f, 0.f, 0.f, 0.f);
    float4 Aw = make_float4(0.f, 0.f, 0.f, 0.f);
    float4 Bw = make_float4(0.f, 0.f, 0.f, 0.f);
    const float* xp = x + (size_t)b0 * DIM + i0;
#pragma unroll 4
    for (int r = 0; r < BROWS; ++r) {
        const float vb = __ldg(&v[b0 + r]);
        const float wb = __ldg(&w[b0 + r]);
        const float4 xv = *(const float4*)(xp + (size_t)r * DIM);
        const float l0 = fmaf(u, xv.x, a);
        const float l1 = fmaf(u, xv.y, a);
        const float l2 = fmaf(u, xv.z, a);
        const float l3 = fmaf(u, xv.w, a);
        const float r0 = fmaxf(l0, 0.f), r1 = fmaxf(l1, 0.f);
        const float r2 = fmaxf(l2, 0.f), r3 = fmaxf(l3, 0.f);
        Av.x = fmaf(vb, r0, Av.x);  Aw.x = fmaf(wb, r0, Aw.x);
        Av.y = fmaf(vb, r1, Av.y);  Aw.y = fmaf(wb, r1, Aw.y);
        Av.z = fmaf(vb, r2, Av.z);  Aw.z = fmaf(wb, r2, Aw.z);
        Av.w = fmaf(vb, r3, Av.w);  Aw.w = fmaf(wb, r3, Aw.w);
        if (l0 > 0.f) { Bv.x += vb; Bw.x += wb; }
        if (l1 > 0.f) { Bv.y += vb; Bw.y += wb; }
        if (l2 > 0.f) { Bv.z += vb; Bw.z += wb; }
        if (l3 > 0.f) { Bv.w += vb; Bw.w += wb; }
    }
    const size_t po = (size_t)blockIdx.y * DIM + i0;
    __stcs((float4*)&g_pAv[po], Av);
    __stcs((float4*)&g_pBv[po], Bv);
    __stcs((float4*)&g_pAw[po], Aw);
    __stcs((float4*)&g_pBw[po], Bw);
}

// ---------------------------------------------------------------------------
// Stage-2: reduce NSLAB slabs -> A/B vectors. 64 blocks x 256 threads.
// Partials read with __ldcs (single use, evict-first; preserve x in L2).
__global__ __launch_bounds__(256) void k_finred4()
{
    __shared__ float sAv[4][64], sBv[4][64], sAw[4][64], sBw[4][64];
    const int col = blockIdx.x * 64 + (threadIdx.x & 63);
    const int grp = threadIdx.x >> 6;                 // 0..3
    const int s0 = grp * (NSLAB / 4);
    float av = 0.f, bv = 0.f, aw = 0.f, bw = 0.f;
#pragma unroll 4
    for (int s = 0; s < NSLAB / 4; ++s) {
        const size_t o = (size_t)(s0 + s) * DIM + col;
        av += __ldcs(&g_pAv[o]); bv += __ldcs(&g_pBv[o]);
        aw += __ldcs(&g_pAw[o]); bw += __ldcs(&g_pBw[o]);
    }
    sAv[grp][threadIdx.x & 63] = av;
    sBv[grp][threadIdx.x & 63] = bv;
    sAw[grp][threadIdx.x & 63] = aw;
    sBw[grp][threadIdx.x & 63] = bw;
    __syncthreads();
    if (grp == 0) {
        const int t = threadIdx.x;                    // 0..63
        g_Av[col] = ((sAv[0][t] + sAv[1][t]) + (sAv[2][t] + sAv[3][t]));
        g_Bv[col] = ((sBv[0][t] + sBv[1][t]) + (sBv[2][t] + sBv[3][t]));
        g_Aw[col] = ((sAw[0][t] + sAw[1][t]) + (sAw[2][t] + sAw[3][t]));
        g_Bw[col] = ((sBw[0][t] + sBw[1][t]) + (sBw[2][t] + sBw[3][t]));
    }
}

// ---------------------------------------------------------------------------
// Scan V[i+1] = Av[i] + Bv[i]*V[i] (V[0]=0) via affine-map composition, then
// W[i+1] = Aw[i] + Bw[i]*V[i], W[0]=0. One block, 1024 threads, 4 elems each.
__global__ __launch_bounds__(1024) void k_scanw()
{
    __shared__ float sa[1024];
    __shared__ float sb[1024];
    const int t = threadIdx.x;
    float la[4], lb[4];
    la[0] = g_Av[4 * t];
    lb[0] = g_Bv[4 * t];
#pragma unroll
    for (int k = 1; k < 4; ++k) {
        const float A = g_Av[4 * t + k];
        const float B = g_Bv[4 * t + k];
        la[k] = fmaf(B, la[k - 1], A);
        lb[k] = B * lb[k - 1];
    }
    sa[t] = la[3];
    sb[t] = lb[3];
    __syncthreads();
#pragma unroll
    for (int off = 1; off < 1024; off <<= 1) {
        float pa = 0.f, pb = 0.f;
        const bool has = (t >= off);
        if (has) { pa = sa[t - off]; pb = sb[t - off]; }
        __syncthreads();
        if (has) {
            sa[t] = fmaf(sb[t], pa, sa[t]);
            sb[t] = sb[t] * pb;
        }
        __syncthreads();
    }
    const float pa = (t > 0) ? sa[t - 1] : 0.f;       // V[4t]
    float V[4];
    V[0] = pa;
#pragma unroll
    for (int k = 1; k < 4; ++k)
        V[k] = fmaf(lb[k - 1], pa, la[k - 1]);
#pragma unroll
    for (int k = 0; k < 4; ++k) {
        const int i = 4 * t + k;
        g_W[i + 1] = fmaf(g_Bw[i], V[k], g_Aw[i]);
    }
    if (t == 0) g_W[0] = 0.f;
}

// ---------------------------------------------------------------------------
// z kernel, one block per row, ROWS IN REVERSE ORDER so the first waves
// consume the x rows most recently cached in L2 by k_red4.
// x read with __ldcs (last use), z written with __stcs (don't evict x).
__global__ __launch_bounds__(256) void k_z(
    const float* __restrict__ x,
    const float* __restrict__ y_p,
    const float* __restrict__ b_p,
    float* __restrict__ out)
{
    const int row = HID - 1 - blockIdx.x;             // reverse order
    const float y0 = y_p[0];
    const float bb = b_p[0];
    const float4* __restrict__ xr = (const float4*)(x + (size_t)row * DIM);
    float4* __restrict__ zr = (float4*)(out + (size_t)row * DIM);
    float cnt = 0.f;
#pragma unroll
    for (int j = 0; j < DIM / 4 / 256; ++j) {   // 4 iterations
        const int c = j * 256 + threadIdx.x;
        const float4 xv = __ldcs(&xr[c]);
        const float4 wv = __ldg((const float4*)&g_W[4 * c]);
        float4 z;
        const float l0 = fmaf(y0, xv.x, wv.x + bb);
        const float l1 = fmaf(y0, xv.y, wv.y + bb);
        const float l2 = fmaf(y0, xv.z, wv.z + bb);
        const float l3 = fmaf(y0, xv.w, wv.w + bb);
        z.x = (l0 >= 0.f) ? l0 : ALPHA * l0; if (l0 < 0.f) cnt += 1.f;
        z.y = (l1 >= 0.f) ? l1 : ALPHA * l1; if (l1 < 0.f) cnt += 1.f;
        z.z = (l2 >= 0.f) ? l2 : ALPHA * l2; if (l2 < 0.f) cnt += 1.f;
        z.w = (l3 >= 0.f) ? l3 : ALPHA * l3; if (l3 < 0.f) cnt += 1.f;
        __stcs(&zr[c], z);
    }
    __shared__ float sm[8];
    const float c = block_reduce_256(cnt, sm);
    if (threadIdx.x == 0)
        out[(size_t)HID * DIM + row] = c * LOG_ALPHA + (float)DIM * logf(fabsf(y0));
}

// ---------------------------------------------------------------------------
extern "C" void kernel_launch(void* const* d_in, const int* in_sizes, int n_in,
                              void* d_out, int out_size)
{
    (void)in_sizes; (void)n_in; (void)out_size;
    const float* x = (const float*)d_in[0];   // [HID, DIM]
    const float* y = (const float*)d_in[1];   // [1]
    const float* w = (const float*)d_in[2];   // [HID]
    const float* b = (const float*)d_in[3];   // [1]
    const float* u = (const float*)d_in[4];   // [1]
    const float* v = (const float*)d_in[5];   // [HID]
    const float* a = (const float*)d_in[6];   // [1]
    float* out = (float*)d_out;               // [HID*DIM] z + [HID] logdet

    k_red4<<<dim3(DIM / ICHUNK, NSLAB), 256>>>(x, v, w, u, a);
    k_finred4<<<DIM / 64, 256>>>();
    k_scanw<<<1, 1024>>>();
    k_z<<<HID, 256>>>(x, y, b, out);
}

// round 7
// speedup vs baseline: 1.4485x; 1.0509x over previous
#include <cuda_runtime.h>
#include <math.h>

#define DIM 4096
#define HID 8192
#define ALPHA 0.1f
#define LOG_ALPHA -2.3025850929940457f

#define GRID  512
#define NTHR  512
#define NSLAB 128              // partial slabs
#define BROWS (HID / NSLAB)    // 64 rows per slab
#define XCH   4                // column chunks in phase 1
#define CCH   (DIM / XCH)      // 1024 cols per chunk

// Scratch (device globals). Partials: 4 x 2MB = 8MB.
static __device__ __align__(16) float g_pAv[(size_t)NSLAB * DIM];
static __device__ __align__(16) float g_pBv[(size_t)NSLAB * DIM];
static __device__ __align__(16) float g_pAw[(size_t)NSLAB * DIM];
static __device__ __align__(16) float g_pBw[(size_t)NSLAB * DIM];
static __device__ __align__(16) float g_Av[DIM];
static __device__ __align__(16) float g_Bv[DIM];
static __device__ __align__(16) float g_Aw[DIM];
static __device__ __align__(16) float g_Bw[DIM];
static __device__ __align__(16) float g_W[DIM + 4];   // W[i], i in [0,DIM]

// Monotonic ticket barrier state. NEVER reset -> safe across graph replays.
static __device__ unsigned long long g_bar = 0ULL;

// ---------------------------------------------------------------------------
// Grid-wide barrier. Tickets of barrier k occupy [k*GRID, (k+1)*GRID) because
// no block can reach barrier k+1 before barrier k releases. Deterministic,
// replay-safe (monotonic counter), graph-capturable (no API calls).
// REQUIRES all GRID blocks co-resident (launch_bounds(512,4): regs<=32 ->
// 4 blocks/SM -> 592 slots >= 512 blocks). Round-6 run confirmed: no hang.
__device__ __forceinline__ void grid_barrier() {
    __syncthreads();
    if (threadIdx.x == 0) {
        __threadfence();                              // release prior writes
        const unsigned long long t = atomicAdd(&g_bar, 1ULL);
        const unsigned long long target = (t / GRID + 1ULL) * GRID;
        while (*((volatile unsigned long long*)&g_bar) < target)
            __nanosleep(64);
        __threadfence();                              // acquire others' writes
    }
    __syncthreads();
}

// ---------------------------------------------------------------------------
__global__ __launch_bounds__(NTHR, 4) void k_fused(
    const float* __restrict__ x,
    const float* __restrict__ v,
    const float* __restrict__ w,
    const float* __restrict__ y_p,
    const float* __restrict__ b_p,
    const float* __restrict__ u_p,
    const float* __restrict__ a_p,
    float* __restrict__ out)
{
    const int tid = threadIdx.x;
    const int bid = blockIdx.x;

    // ============ Phase 1: column statistics, one streaming pass over x ====
    // Block (xc, slab) covers 64 rows x 1024 cols; thread owns 2 columns.
    {
        const float u = u_p[0];
        const float a = a_p[0];
        const int xc = bid & (XCH - 1);
        const int slab = bid >> 2;
        const int col = xc * CCH + tid * 2;
        float av0 = 0.f, av1 = 0.f, bv0 = 0.f, bv1 = 0.f;
        float aw0 = 0.f, aw1 = 0.f, bw0 = 0.f, bw1 = 0.f;
        const float* xp = x + (size_t)slab * BROWS * DIM + col;
        const float* vp = v + slab * BROWS;
        const float* wp = w + slab * BROWS;
#pragma unroll 4
        for (int r = 0; r < BROWS; ++r) {
            const float vb = __ldg(&vp[r]);
            const float wb = __ldg(&wp[r]);
            const float2 xv = *(const float2*)(xp + (size_t)r * DIM);
            const float l0 = fmaf(u, xv.x, a);
            const float l1 = fmaf(u, xv.y, a);
            const float r0 = fmaxf(l0, 0.f);
            const float r1 = fmaxf(l1, 0.f);
            av0 = fmaf(vb, r0, av0);  aw0 = fmaf(wb, r0, aw0);
            av1 = fmaf(vb, r1, av1);  aw1 = fmaf(wb, r1, aw1);
            if (l0 > 0.f) { bv0 += vb; bw0 += wb; }
            if (l1 > 0.f) { bv1 += vb; bw1 += wb; }
        }
        const size_t po = (size_t)slab * DIM + col;
        *(float2*)&g_pAv[po] = make_float2(av0, av1);
        *(float2*)&g_pBv[po] = make_float2(bv0, bv1);
        *(float2*)&g_pAw[po] = make_float2(aw0, aw1);
        *(float2*)&g_pBw[po] = make_float2(bw0, bw1);
    }
    grid_barrier();

    // ============ Phase 2: reduce 128 slabs -> A/B vectors (8 cols/block) ==
    {
        __shared__ float sh[4][64][8];
        const int cl = tid & 7;          // column-local 0..7
        const int j  = tid >> 3;         // 0..63, sums 2 slabs each
        const int col = bid * 8 + cl;
        const size_t o0 = (size_t)(2 * j) * DIM + col;
        const size_t o1 = o0 + DIM;
        sh[0][j][cl] = g_pAv[o0] + g_pAv[o1];
        sh[1][j][cl] = g_pBv[o0] + g_pBv[o1];
        sh[2][j][cl] = g_pAw[o0] + g_pAw[o1];
        sh[3][j][cl] = g_pBw[o0] + g_pBw[o1];
        __syncthreads();
        if (tid < 32) {
            const int arr = tid >> 3;    // 0..3
            const int c = tid & 7;
            float s = 0.f;
#pragma unroll 8
            for (int k = 0; k < 64; ++k)
                s += sh[arr][k][c];
            const int gcol = bid * 8 + c;
            if      (arr == 0) g_Av[gcol] = s;
            else if (arr == 1) g_Bv[gcol] = s;
            else if (arr == 2) g_Aw[gcol] = s;
            else               g_Bw[gcol] = s;
        }
        __syncthreads();
    }
    grid_barrier();

    // ============ Phase 3: affine scan + W (block 0 only) ==================
    // V[i+1] = Av[i] + Bv[i]*V[i], V[0]=0; W[i+1] = Aw[i] + Bw[i]*V[i], W[0]=0
    if (bid == 0) {
        __shared__ float sa[NTHR];
        __shared__ float sb[NTHR];
        float la[8], lb[8];
        const int base = tid * 8;
        la[0] = g_Av[base];
        lb[0] = g_Bv[base];
#pragma unroll
        for (int k = 1; k < 8; ++k) {
            const float A = g_Av[base + k];
            const float B = g_Bv[base + k];
            la[k] = fmaf(B, la[k - 1], A);
            lb[k] = B * lb[k - 1];
        }
        sa[tid] = la[7];
        sb[tid] = lb[7];
        __syncthreads();
#pragma unroll
        for (int off = 1; off < NTHR; off <<= 1) {
            float pa = 0.f, pb = 0.f;
            const bool has = (tid >= off);
            if (has) { pa = sa[tid - off]; pb = sb[tid - off]; }
            __syncthreads();
            if (has) {
                sa[tid] = fmaf(sb[tid], pa, sa[tid]);
                sb[tid] = sb[tid] * pb;
            }
            __syncthreads();
        }
        const float pa = (tid > 0) ? sa[tid - 1] : 0.f;   // V[base]
        float V = pa;
#pragma unroll
        for (int k = 0; k < 8; ++k) {
            const int i = base + k;
            g_W[i + 1] = fmaf(g_Bw[i], V, g_Aw[i]);
            V = fmaf(lb[k], pa, la[k]);                   // V[i+1]
        }
        if (tid == 0) g_W[0] = 0.f;
    }
    grid_barrier();

    // ============ Phase 4: z + logdet (16 rows per block) ==================
    // NOTE: g_W is written in phase 3 of THIS kernel -> must be read through
    // the COHERENT path (plain ld.global). __ldg/ld.global.nc here returns
    // stale data (the round-6 failure).
    {
        __shared__ float smr[16];
        const float y0 = y_p[0];
        const float bb = b_p[0];
        const float ld_base = (float)DIM * logf(fabsf(y0));
        for (int rr = 0; rr < HID / GRID; ++rr) {
            const int row = rr * GRID + bid;
            const float4* __restrict__ xr = (const float4*)(x + (size_t)row * DIM);
            float4* __restrict__ zr = (float4*)(out + (size_t)row * DIM);
            float cnt = 0.f;
#pragma unroll
            for (int it = 0; it < DIM / 4 / NTHR; ++it) {   // 2 iterations
                const int c = it * NTHR + tid;
                const float4 xv = __ldcs(&xr[c]);
                const float4 wv = *(const float4*)&g_W[4 * c];   // coherent load
                float4 z;
                const float l0 = fmaf(y0, xv.x, wv.x + bb);
                const float l1 = fmaf(y0, xv.y, wv.y + bb);
                const float l2 = fmaf(y0, xv.z, wv.z + bb);
                const float l3 = fmaf(y0, xv.w, wv.w + bb);
                z.x = (l0 >= 0.f) ? l0 : ALPHA * l0; if (l0 < 0.f) cnt += 1.f;
                z.y = (l1 >= 0.f) ? l1 : ALPHA * l1; if (l1 < 0.f) cnt += 1.f;
                z.z = (l2 >= 0.f) ? l2 : ALPHA * l2; if (l2 < 0.f) cnt += 1.f;
                z.w = (l3 >= 0.f) ? l3 : ALPHA * l3; if (l3 < 0.f) cnt += 1.f;
                __stcs(&zr[c], z);
            }
            // block reduce over 512 threads (16 warps)
#pragma unroll
            for (int o = 16; o > 0; o >>= 1)
                cnt += __shfl_xor_sync(0xffffffffu, cnt, o);
            if ((tid & 31) == 0) smr[tid >> 5] = cnt;
            __syncthreads();
            if (tid < 32) {
                float s = (tid < 16) ? smr[tid] : 0.f;
#pragma unroll
                for (int o = 8; o > 0; o >>= 1)
                    s += __shfl_xor_sync(0xffffffffu, s, o);
                if (tid == 0)
                    out[(size_t)HID * DIM + row] = s * LOG_ALPHA + ld_base;
            }
            __syncthreads();
        }
    }
}

// ---------------------------------------------------------------------------
extern "C" void kernel_launch(void* const* d_in, const int* in_sizes, int n_in,
                              void* d_out, int out_size)
{
    (void)in_sizes; (void)n_in; (void)out_size;
    const float* x = (const float*)d_in[0];   // [HID, DIM]
    const float* y = (const float*)d_in[1];   // [1]
    const float* w = (const float*)d_in[2];   // [HID]
    const float* b = (const float*)d_in[3];   // [1]
    const float* u = (const float*)d_in[4];   // [1]
    const float* v = (const float*)d_in[5];   // [HID]
    const float* a = (const float*)d_in[6];   // [1]
    float* out = (float*)d_out;               // [HID*DIM] z + [HID] logdet

    k_fused<<<GRID, NTHR>>>(x, v, w, y, b, u, a, out);
}